// round 1
// baseline (speedup 1.0000x reference)
#include <cuda_runtime.h>
#include <cstdint>

// ============================================================================
// NSLayer: out = x + Mat @ x, Mat = sum_{k=1..7} w[k-1] A^k + w[7] I,
// A = I - x x^T (per 8x8 matrix, batch 262144).
//
// Identity: A^k x = x * (I - x^T x)^k.  Let Shat = I - x^T x (8x8).
// out = x @ ((1 + w7) I + w0*Shat + w1*Shat^2 + ... + w6*Shat^7)
// Right-Horner: V = w6*x; V = V@Shat + w5*x; ...; V = V@Shat + w0*x; V = V@Shat;
// out = (1+w7)*x + V.
// 8 total 8x8x8 matmuls, all register-resident, one thread per matrix.
// fp32 math done with packed fma.rn.f32x2 (Blackwell f32x2 pipe, 2x FFMA rate).
// ============================================================================

typedef unsigned long long F2;  // carrier for a packed float2 in a 64-bit reg

__device__ __forceinline__ F2 fma2(F2 a, F2 b, F2 c) {
    F2 d;
    asm("fma.rn.f32x2 %0, %1, %2, %3;" : "=l"(d) : "l"(a), "l"(b), "l"(c));
    return d;
}
__device__ __forceinline__ F2 mul2(F2 a, F2 b) {
    F2 d;
    asm("mul.rn.f32x2 %0, %1, %2;" : "=l"(d) : "l"(a), "l"(b));
    return d;
}
// pack (v, v) into a 64-bit register pair
__device__ __forceinline__ F2 bc2(float v) {
    union { F2 u; float f[2]; } c;
    c.f[0] = v; c.f[1] = v;
    return c.u;
}
// pack two floats
__device__ __forceinline__ F2 mkp(float a, float b) {
    union { F2 u; float f[2]; } c;
    c.f[0] = a; c.f[1] = b;
    return c.u;
}
// extract half h (compile-time constant after unroll)
__device__ __forceinline__ float getf(F2 p, int h) {
    union { F2 u; float f[2]; } c;
    c.u = p;
    return c.f[h];
}

__global__ void __launch_bounds__(128, 1)
ns_kernel(const float* __restrict__ in, const float* __restrict__ wt,
          float* __restrict__ out, int nmat) {
    int m = blockIdx.x * 128 + threadIdx.x;
    if (m >= nmat) return;

    // ---- weights (uniform broadcast loads) ----
    float wv[8];
#pragma unroll
    for (int j = 0; j < 8; j++) wv[j] = __ldg(wt + j);

    // ---- load x: 8x8 floats as 32 packed pairs (row i, col-pair jp) ----
    // xp[i*4 + jp] = (x[i][2jp], x[i][2jp+1])
    F2 xp[32];
    {
        const ulonglong2* p = reinterpret_cast<const ulonglong2*>(in) + (size_t)m * 16;
#pragma unroll
        for (int q = 0; q < 16; q++) {
            ulonglong2 v = p[q];
            xp[2 * q]     = v.x;
            xp[2 * q + 1] = v.y;
        }
    }

    // ---- Shat = I - x^T x : sp[k*4 + jp] = (Shat[k][2jp], Shat[k][2jp+1]) ----
    F2 sp[32];
    const F2 NEG1 = bc2(-1.0f);
#pragma unroll
    for (int k = 0; k < 8; k++) {
        F2 a0 = 0, a1 = 0, a2 = 0, a3 = 0;  // 0ull == (0.f, 0.f)
#pragma unroll
        for (int i = 0; i < 8; i++) {
            F2 b = bc2(getf(xp[i * 4 + (k >> 1)], k & 1));  // x[i][k] broadcast
            a0 = fma2(b, xp[i * 4 + 0], a0);
            a1 = fma2(b, xp[i * 4 + 1], a1);
            a2 = fma2(b, xp[i * 4 + 2], a2);
            a3 = fma2(b, xp[i * 4 + 3], a3);
        }
        // Shat[k][j] = (k==j) - S[k][j]
#pragma unroll
        for (int jp = 0; jp < 4; jp++) {
            float e0 = (k == 2 * jp) ? 1.0f : 0.0f;
            float e1 = (k == 2 * jp + 1) ? 1.0f : 0.0f;
            F2 a = (jp == 0) ? a0 : (jp == 1) ? a1 : (jp == 2) ? a2 : a3;
            sp[k * 4 + jp] = fma2(a, NEG1, mkp(e0, e1));
        }
    }

    // ---- Horner: V = w6*x; 6x {V = V@Shat + w_k*x}; V = V@Shat ----
    F2 up[32];
    {
        F2 wp = bc2(wv[6]);
#pragma unroll
        for (int q = 0; q < 32; q++) up[q] = mul2(wp, xp[q]);
    }

#pragma unroll
    for (int s = 0; s < 7; s++) {
        float wk = (s < 6) ? wv[5 - s] : 0.0f;
        F2 wkp = bc2(wk);
#pragma unroll
        for (int i = 0; i < 8; i++) {
            // row i of new V; depends only on row i of old V -> in-place per row
            F2 t0 = mul2(wkp, xp[i * 4 + 0]);
            F2 t1 = mul2(wkp, xp[i * 4 + 1]);
            F2 t2 = mul2(wkp, xp[i * 4 + 2]);
            F2 t3 = mul2(wkp, xp[i * 4 + 3]);
#pragma unroll
            for (int k = 0; k < 8; k++) {
                F2 b = bc2(getf(up[i * 4 + (k >> 1)], k & 1));  // V[i][k] broadcast
                t0 = fma2(b, sp[k * 4 + 0], t0);
                t1 = fma2(b, sp[k * 4 + 1], t1);
                t2 = fma2(b, sp[k * 4 + 2], t2);
                t3 = fma2(b, sp[k * 4 + 3], t3);
            }
            up[i * 4 + 0] = t0;
            up[i * 4 + 1] = t1;
            up[i * 4 + 2] = t2;
            up[i * 4 + 3] = t3;
        }
    }

    // ---- out = (1 + w7)*x + V ----
    {
        F2 fp = bc2(1.0f + wv[7]);
#pragma unroll
        for (int q = 0; q < 32; q++) up[q] = fma2(fp, xp[q], up[q]);
    }

    // ---- store ----
    {
        ulonglong2* p = reinterpret_cast<ulonglong2*>(out) + (size_t)m * 16;
#pragma unroll
        for (int q = 0; q < 16; q++) {
            ulonglong2 v;
            v.x = up[2 * q];
            v.y = up[2 * q + 1];
            p[q] = v;
        }
    }
}

extern "C" void kernel_launch(void* const* d_in, const int* in_sizes, int n_in,
                              void* d_out, int out_size) {
    const float* in = (const float*)d_in[0];
    const float* wt = (const float*)d_in[1];
    float* out = (float*)d_out;
    int nmat = in_sizes[0] / 64;  // 262144 8x8 matrices
    int threads = 128;
    int blocks = (nmat + threads - 1) / threads;
    ns_kernel<<<blocks, threads>>>(in, wt, out, nmat);
}

// round 2
// speedup vs baseline: 1.2955x; 1.2955x over previous
#include <cuda_runtime.h>
#include <cstdint>

// ============================================================================
// NSLayer: out = x + Mat @ x, Mat = sum_{k=1..7} w[k-1] A^k + w[7] I,
// A = I - x x^T (per 8x8 matrix, batch 262144).
//
// Identity: A^k x = x (I - x^T x)^k.  Let Shat = I - x^T x.
// out = x @ P(Shat),  P(S) = (1+w7) I + sum_{k=1..7} w[k-1] S^k.
// Matrix Horner in Shat-space (only Shat and M live; x streamed):
//   M = w6*Shat + w5*I
//   M = M*Shat + c_k*I   for c = w4, w3, w2, w1, w0, (1+w7)   (6 steps)
//   out_row_i = x_row_i @ M                                   (x reloaded, L2 hit)
// All math in packed fma.rn.f32x2 (Blackwell f32x2 pipe, 2x FFMA rate).
// Peak live set ~68 F2 pairs (136 regs) -> no spills, 3 CTAs/SM.
// ============================================================================

typedef unsigned long long F2;  // packed float2 carrier

__device__ __forceinline__ F2 fma2(F2 a, F2 b, F2 c) {
    F2 d;
    asm("fma.rn.f32x2 %0, %1, %2, %3;" : "=l"(d) : "l"(a), "l"(b), "l"(c));
    return d;
}
__device__ __forceinline__ F2 mul2(F2 a, F2 b) {
    F2 d;
    asm("mul.rn.f32x2 %0, %1, %2;" : "=l"(d) : "l"(a), "l"(b));
    return d;
}
__device__ __forceinline__ F2 bc2(float v) {
    union { F2 u; float f[2]; } c;
    c.f[0] = v; c.f[1] = v;
    return c.u;
}
__device__ __forceinline__ F2 mkp(float a, float b) {
    union { F2 u; float f[2]; } c;
    c.f[0] = a; c.f[1] = b;
    return c.u;
}
__device__ __forceinline__ float getf(F2 p, int h) {
    union { F2 u; float f[2]; } c;
    c.u = p;
    return c.f[h];
}

__global__ void __launch_bounds__(128, 3)
ns_kernel(const float* __restrict__ in, const float* __restrict__ wt,
          float* __restrict__ out, int nmat) {
    int m = blockIdx.x * 128 + threadIdx.x;
    if (m >= nmat) return;

    float wv[8];
#pragma unroll
    for (int j = 0; j < 8; j++) wv[j] = __ldg(wt + j);

    const ulonglong2* xin = reinterpret_cast<const ulonglong2*>(in) + (size_t)m * 16;

    // ---- Phase 1: S = x^T x, streamed rank-1 accumulation ----
    // sp[k*4+jp] = (S[k][2jp], S[k][2jp+1])
    F2 sp[32];
#pragma unroll
    for (int q = 0; q < 32; q++) sp[q] = 0;  // 0ull == (0.f, 0.f)

#pragma unroll
    for (int i = 0; i < 8; i++) {
        ulonglong2 r0 = xin[2 * i];
        ulonglong2 r1 = xin[2 * i + 1];
        F2 row[4] = { r0.x, r0.y, r1.x, r1.y };
#pragma unroll
        for (int k = 0; k < 8; k++) {
            F2 b = bc2(getf(row[k >> 1], k & 1));  // x[i][k]
            sp[k * 4 + 0] = fma2(b, row[0], sp[k * 4 + 0]);
            sp[k * 4 + 1] = fma2(b, row[1], sp[k * 4 + 1]);
            sp[k * 4 + 2] = fma2(b, row[2], sp[k * 4 + 2]);
            sp[k * 4 + 3] = fma2(b, row[3], sp[k * 4 + 3]);
        }
    }

    // ---- Shat = I - S (in place) ----
    const F2 NEG1 = bc2(-1.0f);
#pragma unroll
    for (int k = 0; k < 8; k++) {
#pragma unroll
        for (int jp = 0; jp < 4; jp++) {
            float e0 = (k == 2 * jp) ? 1.0f : 0.0f;
            float e1 = (k == 2 * jp + 1) ? 1.0f : 0.0f;
            sp[k * 4 + jp] = fma2(sp[k * 4 + jp], NEG1, mkp(e0, e1));
        }
    }

    // ---- M = w6*Shat + w5*I ----
    F2 mm[32];
    {
        F2 w6p = bc2(wv[6]);
#pragma unroll
        for (int k = 0; k < 8; k++) {
#pragma unroll
            for (int jp = 0; jp < 4; jp++) {
                float e0 = (k == 2 * jp) ? wv[5] : 0.0f;
                float e1 = (k == 2 * jp + 1) ? wv[5] : 0.0f;
                mm[k * 4 + jp] = fma2(w6p, sp[k * 4 + jp], mkp(e0, e1));
            }
        }
    }

    // ---- 6 Horner steps: M = M*Shat + c*I (row-wise in place) ----
    float addc[6] = { wv[4], wv[3], wv[2], wv[1], wv[0], 1.0f + wv[7] };
#pragma unroll
    for (int s = 0; s < 6; s++) {
        float c = addc[s];
#pragma unroll
        for (int i = 0; i < 8; i++) {
            // init accumulators with c * e_i at the diagonal position
            F2 t0 = (i < 2) ? mkp((i == 0) ? c : 0.0f, (i == 1) ? c : 0.0f) : (F2)0;
            F2 t1 = (i >= 2 && i < 4) ? mkp((i == 2) ? c : 0.0f, (i == 3) ? c : 0.0f) : (F2)0;
            F2 t2 = (i >= 4 && i < 6) ? mkp((i == 4) ? c : 0.0f, (i == 5) ? c : 0.0f) : (F2)0;
            F2 t3 = (i >= 6) ? mkp((i == 6) ? c : 0.0f, (i == 7) ? c : 0.0f) : (F2)0;
#pragma unroll
            for (int k = 0; k < 8; k++) {
                F2 b = bc2(getf(mm[i * 4 + (k >> 1)], k & 1));  // M[i][k]
                t0 = fma2(b, sp[k * 4 + 0], t0);
                t1 = fma2(b, sp[k * 4 + 1], t1);
                t2 = fma2(b, sp[k * 4 + 2], t2);
                t3 = fma2(b, sp[k * 4 + 3], t3);
            }
            mm[i * 4 + 0] = t0;
            mm[i * 4 + 1] = t1;
            mm[i * 4 + 2] = t2;
            mm[i * 4 + 3] = t3;
        }
    }

    // ---- Phase 3: out row i = x_row_i @ M  (x reloaded; L2-resident) ----
    ulonglong2* op = reinterpret_cast<ulonglong2*>(out) + (size_t)m * 16;
#pragma unroll
    for (int i = 0; i < 8; i++) {
        ulonglong2 r0 = xin[2 * i];
        ulonglong2 r1 = xin[2 * i + 1];
        F2 row[4] = { r0.x, r0.y, r1.x, r1.y };
        F2 t0 = 0, t1 = 0, t2 = 0, t3 = 0;
#pragma unroll
        for (int k = 0; k < 8; k++) {
            F2 b = bc2(getf(row[k >> 1], k & 1));  // x[i][k]
            t0 = fma2(b, mm[k * 4 + 0], t0);
            t1 = fma2(b, mm[k * 4 + 1], t1);
            t2 = fma2(b, mm[k * 4 + 2], t2);
            t3 = fma2(b, mm[k * 4 + 3], t3);
        }
        ulonglong2 v0, v1;
        v0.x = t0; v0.y = t1;
        v1.x = t2; v1.y = t3;
        op[2 * i] = v0;
        op[2 * i + 1] = v1;
    }
}

extern "C" void kernel_launch(void* const* d_in, const int* in_sizes, int n_in,
                              void* d_out, int out_size) {
    const float* in = (const float*)d_in[0];
    const float* wt = (const float*)d_in[1];
    float* out = (float*)d_out;
    int nmat = in_sizes[0] / 64;  // 262144 matrices
    int threads = 128;
    int blocks = (nmat + threads - 1) / threads;
    ns_kernel<<<blocks, threads>>>(in, wt, out, nmat);
}

// round 3
// speedup vs baseline: 1.4280x; 1.1023x over previous
#include <cuda_runtime.h>
#include <cstdint>

// ============================================================================
// NSLayer: out = x + Mat @ x,  A = I - x x^T,  Mat = sum w[k-1] A^k + w7 I.
// Identity: A^k x = x (I - x^T x)^k.  Shat = I - x^T x (8x8).
// out = x @ P(Shat), matrix-Horner in Shat-space, one thread per matrix.
// f32x2 packed FMA throughout.
//
// R3 change: global<->register traffic was fully uncoalesced (thread-per-
// matrix, 256B apart -> 32 L1 wavefronts per warp access, ~47us of L1
// serialization). Now staged through shared memory: coalesced LDG/STG,
// per-matrix smem stride 68 floats (bank-conflict-free LDS.128).
// ============================================================================

typedef unsigned long long F2;  // packed float2 carrier

__device__ __forceinline__ F2 fma2(F2 a, F2 b, F2 c) {
    F2 d;
    asm("fma.rn.f32x2 %0, %1, %2, %3;" : "=l"(d) : "l"(a), "l"(b), "l"(c));
    return d;
}
__device__ __forceinline__ F2 bc2(float v) {
    union { F2 u; float f[2]; } c;
    c.f[0] = v; c.f[1] = v;
    return c.u;
}
__device__ __forceinline__ F2 mkp(float a, float b) {
    union { F2 u; float f[2]; } c;
    c.f[0] = a; c.f[1] = b;
    return c.u;
}
__device__ __forceinline__ float getf(F2 p, int h) {
    union { F2 u; float f[2]; } c;
    c.u = p;
    return c.f[h];
}

static constexpr int MPB = 128;      // matrices per block (== threads)
static constexpr int STRIDE = 68;    // floats per matrix in smem (68%32=4 -> LDS.128 conflict-free)

__global__ void __launch_bounds__(128, 3)
ns_kernel(const float* __restrict__ in, const float* __restrict__ wt,
          float* __restrict__ out) {
    __shared__ float buf[MPB * STRIDE];  // 34,816 B

    const int tid = threadIdx.x;
    const size_t ctaBase = (size_t)blockIdx.x * MPB * 64;  // floats

    // ---- coalesced load: CTA tile = 128*64 floats = 2048 float4s ----
    {
        const float4* gin = reinterpret_cast<const float4*>(in + ctaBase);
#pragma unroll
        for (int i = 0; i < 16; i++) {
            int g = i * MPB + tid;             // float4 index in tile
            float4 v = gin[g];
            int m = g >> 4;                    // matrix within tile
            int off = (g & 15) << 2;           // float offset in matrix
            *reinterpret_cast<float4*>(&buf[m * STRIDE + off]) = v;
        }
    }
    __syncthreads();

    float wv[8];
#pragma unroll
    for (int j = 0; j < 8; j++) wv[j] = __ldg(wt + j);

    float* mybuf = &buf[tid * STRIDE];

    // ---- Phase 1: S = x^T x, streamed rank-1 from smem rows ----
    F2 sp[32];
#pragma unroll
    for (int q = 0; q < 32; q++) sp[q] = 0;

#pragma unroll
    for (int i = 0; i < 8; i++) {
        ulonglong2 r0 = *reinterpret_cast<const ulonglong2*>(&mybuf[i * 8]);
        ulonglong2 r1 = *reinterpret_cast<const ulonglong2*>(&mybuf[i * 8 + 4]);
        F2 row[4] = { r0.x, r0.y, r1.x, r1.y };
#pragma unroll
        for (int k = 0; k < 8; k++) {
            F2 b = bc2(getf(row[k >> 1], k & 1));  // x[i][k]
            sp[k * 4 + 0] = fma2(b, row[0], sp[k * 4 + 0]);
            sp[k * 4 + 1] = fma2(b, row[1], sp[k * 4 + 1]);
            sp[k * 4 + 2] = fma2(b, row[2], sp[k * 4 + 2]);
            sp[k * 4 + 3] = fma2(b, row[3], sp[k * 4 + 3]);
        }
    }

    // ---- Shat = I - S ----
    const F2 NEG1 = bc2(-1.0f);
#pragma unroll
    for (int k = 0; k < 8; k++) {
#pragma unroll
        for (int jp = 0; jp < 4; jp++) {
            float e0 = (k == 2 * jp) ? 1.0f : 0.0f;
            float e1 = (k == 2 * jp + 1) ? 1.0f : 0.0f;
            sp[k * 4 + jp] = fma2(sp[k * 4 + jp], NEG1, mkp(e0, e1));
        }
    }

    // ---- M = w6*Shat + w5*I ----
    F2 mm[32];
    {
        F2 w6p = bc2(wv[6]);
#pragma unroll
        for (int k = 0; k < 8; k++) {
#pragma unroll
            for (int jp = 0; jp < 4; jp++) {
                float e0 = (k == 2 * jp) ? wv[5] : 0.0f;
                float e1 = (k == 2 * jp + 1) ? wv[5] : 0.0f;
                mm[k * 4 + jp] = fma2(w6p, sp[k * 4 + jp], mkp(e0, e1));
            }
        }
    }

    // ---- 6 Horner steps: M = M*Shat + c*I (row-wise in place) ----
    float addc[6] = { wv[4], wv[3], wv[2], wv[1], wv[0], 1.0f + wv[7] };
#pragma unroll
    for (int s = 0; s < 6; s++) {
        float c = addc[s];
#pragma unroll
        for (int i = 0; i < 8; i++) {
            F2 t0 = (i < 2) ? mkp((i == 0) ? c : 0.0f, (i == 1) ? c : 0.0f) : (F2)0;
            F2 t1 = (i >= 2 && i < 4) ? mkp((i == 2) ? c : 0.0f, (i == 3) ? c : 0.0f) : (F2)0;
            F2 t2 = (i >= 4 && i < 6) ? mkp((i == 4) ? c : 0.0f, (i == 5) ? c : 0.0f) : (F2)0;
            F2 t3 = (i >= 6) ? mkp((i == 6) ? c : 0.0f, (i == 7) ? c : 0.0f) : (F2)0;
#pragma unroll
            for (int k = 0; k < 8; k++) {
                F2 b = bc2(getf(mm[i * 4 + (k >> 1)], k & 1));  // M[i][k]
                t0 = fma2(b, sp[k * 4 + 0], t0);
                t1 = fma2(b, sp[k * 4 + 1], t1);
                t2 = fma2(b, sp[k * 4 + 2], t2);
                t3 = fma2(b, sp[k * 4 + 3], t3);
            }
            mm[i * 4 + 0] = t0;
            mm[i * 4 + 1] = t1;
            mm[i * 4 + 2] = t2;
            mm[i * 4 + 3] = t3;
        }
    }

    // ---- Phase 3: out row i = x_row_i @ M, overwrite row in smem ----
#pragma unroll
    for (int i = 0; i < 8; i++) {
        ulonglong2 r0 = *reinterpret_cast<const ulonglong2*>(&mybuf[i * 8]);
        ulonglong2 r1 = *reinterpret_cast<const ulonglong2*>(&mybuf[i * 8 + 4]);
        F2 row[4] = { r0.x, r0.y, r1.x, r1.y };
        F2 t0 = 0, t1 = 0, t2 = 0, t3 = 0;
#pragma unroll
        for (int k = 0; k < 8; k++) {
            F2 b = bc2(getf(row[k >> 1], k & 1));  // x[i][k]
            t0 = fma2(b, mm[k * 4 + 0], t0);
            t1 = fma2(b, mm[k * 4 + 1], t1);
            t2 = fma2(b, mm[k * 4 + 2], t2);
            t3 = fma2(b, mm[k * 4 + 3], t3);
        }
        ulonglong2 v0, v1;
        v0.x = t0; v0.y = t1;
        v1.x = t2; v1.y = t3;
        *reinterpret_cast<ulonglong2*>(&mybuf[i * 8]) = v0;
        *reinterpret_cast<ulonglong2*>(&mybuf[i * 8 + 4]) = v1;
    }
    __syncthreads();

    // ---- coalesced store ----
    {
        float4* gout = reinterpret_cast<float4*>(out + ctaBase);
#pragma unroll
        for (int i = 0; i < 16; i++) {
            int g = i * MPB + tid;
            int m = g >> 4;
            int off = (g & 15) << 2;
            gout[g] = *reinterpret_cast<const float4*>(&buf[m * STRIDE + off]);
        }
    }
}

extern "C" void kernel_launch(void* const* d_in, const int* in_sizes, int n_in,
                              void* d_out, int out_size) {
    const float* in = (const float*)d_in[0];
    const float* wt = (const float*)d_in[1];
    float* out = (float*)d_out;
    int nmat = in_sizes[0] / 64;           // 262144, divisible by 128
    int blocks = nmat / MPB;               // 2048
    ns_kernel<<<blocks, MPB>>>(in, wt, out);
}